// round 12
// baseline (speedup 1.0000x reference)
#include <cuda_runtime.h>
#include <cuda_bf16.h>
#include <math.h>
#include <stdint.h>

typedef __nv_bfloat16 bf16;

#define BB 2
#define NN 2048
#define HH 16
#define MTOT (BB*NN)          // 4096
#define BHT (BB*HH)           // 32

// ======================= scratch (no cudaMalloc allowed) =======================
__device__ __align__(256) bf16  g_xh[(size_t)MTOT * 1024];
__device__ __align__(256) bf16  g_xl[(size_t)MTOT * 1024];
__device__ __align__(256) bf16  g_wqTh[(size_t)3072 * 1024];
__device__ __align__(256) bf16  g_wqTl[(size_t)3072 * 1024];
__device__ __align__(256) bf16  g_woTh[(size_t)1024 * 1024];
__device__ __align__(256) bf16  g_woTl[(size_t)1024 * 1024];
__device__ __align__(256) bf16  g_Qh[(size_t)BHT * NN * 64];
__device__ __align__(256) bf16  g_Ql[(size_t)BHT * NN * 64];
__device__ __align__(256) bf16  g_Kh[(size_t)BHT * NN * 64];
__device__ __align__(256) bf16  g_Kl[(size_t)BHT * NN * 64];
__device__ __align__(256) bf16  g_Vth[(size_t)BHT * 64 * NN];   // [bh, d, n]
__device__ __align__(256) bf16  g_Vtl[(size_t)BHT * 64 * NN];
__device__ __align__(256) bf16  g_aOh[(size_t)MTOT * 1024];
__device__ __align__(256) bf16  g_aOl[(size_t)MTOT * 1024];
__device__ __align__(256) float g_cs[(size_t)NN * 32 * 2];      // rope cos/sin table

// ======================= helpers =======================
__device__ __forceinline__ uint32_t smem_to_u32(const void* p) {
    uint32_t a;
    asm("{ .reg .u64 t; cvta.to.shared.u64 t, %1; cvt.u32.u64 %0, t; }" : "=r"(a) : "l"(p));
    return a;
}
__device__ __forceinline__ void cp16(uint32_t s, const void* g) {
    asm volatile("cp.async.cg.shared.global [%0], [%1], 16;" :: "r"(s), "l"(g) : "memory");
}
__device__ __forceinline__ void ldm_x4(uint32_t* r, uint32_t addr) {
    asm volatile("ldmatrix.sync.aligned.m8n8.x4.shared.b16 {%0,%1,%2,%3}, [%4];"
                 : "=r"(r[0]), "=r"(r[1]), "=r"(r[2]), "=r"(r[3]) : "r"(addr));
}
__device__ __forceinline__ void mma16816(float* d, const uint32_t* a,
                                         uint32_t b0, uint32_t b1) {
    asm volatile(
        "mma.sync.aligned.m16n8k16.row.col.f32.bf16.bf16.f32 "
        "{%0,%1,%2,%3}, {%4,%5,%6,%7}, {%8,%9}, {%0,%1,%2,%3};"
        : "+f"(d[0]), "+f"(d[1]), "+f"(d[2]), "+f"(d[3])
        : "r"(a[0]), "r"(a[1]), "r"(a[2]), "r"(a[3]), "r"(b0), "r"(b1));
}
__device__ __forceinline__ float ex2(float x) {
    float y;
    asm("ex2.approx.f32 %0, %1;" : "=f"(y) : "f"(x));
    return y;
}
__device__ __forceinline__ void split2(float v, bf16* H, bf16* L, size_t o) {
    bf16 hb = __float2bfloat16(v);
    H[o] = hb;
    L[o] = __float2bfloat16(v - __bfloat162float(hb));
}
// swizzle for 64B-wide rows (GEMM tiles): 16B-unit col xored with (row>>1)&3
__device__ __forceinline__ uint32_t sw64(int row, int c16) {
    return (uint32_t)(row * 64 + ((c16 ^ ((row >> 1) & 3)) << 4));
}
// standard 128B swizzle for 128B-wide rows (flash tiles)
__device__ __forceinline__ uint32_t sw128(uint32_t off) {
    return off ^ ((off >> 3) & 0x70);
}

// ======================= HMMA bf16-split GEMM =======================
// C = (Ah+Al)[M,K] @ (Bh+Bl)[N,K]^T.  128x128 tile, BK=32, 256 thr, 3-stage.
// Product-major MMA order: consecutive MMAs always hit different accumulators.
// EPI=0: write fp32 C.  EPI=1: fused rope/split/transpose epilogue for qkv.
template <int EPI>
__global__ __launch_bounds__(256)
void mma_gemm_kernel(const bf16* __restrict__ Ah, const bf16* __restrict__ Al,
                     const bf16* __restrict__ Bh, const bf16* __restrict__ Bl,
                     float* __restrict__ C, int K, int ldC,
                     const float* __restrict__ cs,
                     bf16* __restrict__ Qh, bf16* __restrict__ Ql,
                     bf16* __restrict__ Kh, bf16* __restrict__ Kl,
                     bf16* __restrict__ Vth, bf16* __restrict__ Vtl) {
    constexpr int TN = 128;
    constexpr int WNW = TN / 4;
    constexpr int NG  = WNW / 16;
    constexpr int NT  = WNW / 8;
    constexpr int ABYTES = 128 * 64;   // 8192
    constexpr int BBYTES = TN * 64;
    constexpr int STAGE  = 2 * ABYTES + 2 * BBYTES;

    extern __shared__ char smem[];
    uint32_t sb = smem_to_u32(smem);

    int tid = threadIdx.x;
    int lane = tid & 31, wid = tid >> 5;
    int wm = wid & 1, wn = wid >> 1;

    int n0 = blockIdx.x * TN;
    int m0 = blockIdx.y * 128;

    float acc[4][NT][4];
#pragma unroll
    for (int i = 0; i < 4; i++)
#pragma unroll
        for (int j = 0; j < NT; j++)
#pragma unroll
            for (int c = 0; c < 4; c++) acc[i][j][c] = 0.f;

    const int nkt = K >> 5;

    auto load_tiles = [&](int kt, int buf) {
        uint32_t base = sb + buf * STAGE;
#pragma unroll
        for (int it = 0; it < 2; it++) {
            int i = tid + it * 256;
            int r = i >> 2, c = i & 3;
            size_t g = (size_t)(m0 + r) * K + (size_t)kt * 32 + c * 8;
            uint32_t so = base + sw64(r, c);
            cp16(so, Ah + g);
            cp16(so + ABYTES, Al + g);
        }
#pragma unroll
        for (int it = 0; it < 2; it++) {
            int i = tid + it * 256;
            int r = i >> 2, c = i & 3;
            size_t g = (size_t)(n0 + r) * K + (size_t)kt * 32 + c * 8;
            uint32_t so = base + 2 * ABYTES + sw64(r, c);
            cp16(so, Bh + g);
            cp16(so + BBYTES, Bl + g);
        }
    };

    load_tiles(0, 0);
    asm volatile("cp.async.commit_group;" ::: "memory");
    if (nkt > 1) {
        load_tiles(1, 1);
        asm volatile("cp.async.commit_group;" ::: "memory");
    }

    int stage = 0;
    for (int kt = 0; kt < nkt; kt++) {
        if (kt < nkt - 1) {
            asm volatile("cp.async.wait_group 1;" ::: "memory");
        } else {
            asm volatile("cp.async.wait_group 0;" ::: "memory");
        }
        __syncthreads();

        if (kt + 2 < nkt) {
            int nb = stage + 2; if (nb >= 3) nb -= 3;
            load_tiles(kt + 2, nb);
            asm volatile("cp.async.commit_group;" ::: "memory");
        }

        uint32_t abase = sb + stage * STAGE;
        uint32_t bbase = abase + 2 * ABYTES;

#pragma unroll
        for (int ks = 0; ks < 2; ks++) {
            int arow = wm * 64 + (lane & 15);
            int c16  = ks * 2 + (lane >> 4);

            uint32_t ah[4][4], al[4][4];
#pragma unroll
            for (int i = 0; i < 4; i++) {
                uint32_t ad = abase + sw64(arow + i * 16, c16);
                ldm_x4(ah[i], ad);
                ldm_x4(al[i], ad + ABYTES);
            }

            uint32_t bh[NG][4], bl[NG][4];
            int brow = wn * WNW + (lane & 15);
#pragma unroll
            for (int g = 0; g < NG; g++) {
                uint32_t bd = bbase + sw64(brow + g * 16, c16);
                ldm_x4(bh[g], bd);
                ldm_x4(bl[g], bd + BBYTES);
            }

            // product-major: 16 independent MMAs per pass, acc reuse distance 16
#pragma unroll
            for (int i = 0; i < 4; i++)
#pragma unroll
                for (int j = 0; j < NT; j++) {
                    int g = j >> 1, hf = j & 1;
                    mma16816(acc[i][j], ah[i], bh[g][hf], bh[g][hf + 2]);
                }
#pragma unroll
            for (int i = 0; i < 4; i++)
#pragma unroll
                for (int j = 0; j < NT; j++) {
                    int g = j >> 1, hf = j & 1;
                    mma16816(acc[i][j], ah[i], bl[g][hf], bl[g][hf + 2]);
                }
#pragma unroll
            for (int i = 0; i < 4; i++)
#pragma unroll
                for (int j = 0; j < NT; j++) {
                    int g = j >> 1, hf = j & 1;
                    mma16816(acc[i][j], al[i], bh[g][hf], bh[g][hf + 2]);
                }
        }
        if (++stage == 3) stage = 0;
    }

    int r0 = lane >> 2, c0 = (lane & 3) * 2;

    if (EPI == 0) {
#pragma unroll
        for (int i = 0; i < 4; i++) {
            int row = m0 + wm * 64 + i * 16 + r0;
#pragma unroll
            for (int j = 0; j < NT; j++) {
                int col = n0 + wn * WNW + j * 8 + c0;
                *(float2*)&C[(size_t)row * ldC + col] =
                    make_float2(acc[i][j][0], acc[i][j][1]);
                *(float2*)&C[(size_t)(row + 8) * ldC + col] =
                    make_float2(acc[i][j][2], acc[i][j][3]);
            }
        }
        return;
    }

    // ===== fused qkv epilogue: stage acc tile through smem (128 x 129 f32) =====
    __syncthreads();
    float* st = (float*)smem;
#pragma unroll
    for (int i = 0; i < 4; i++) {
        int row = wm * 64 + i * 16 + r0;
#pragma unroll
        for (int j = 0; j < NT; j++) {
            int col = wn * WNW + j * 8 + c0;
            st[row * 129 + col]           = acc[i][j][0];
            st[row * 129 + col + 1]       = acc[i][j][1];
            st[(row + 8) * 129 + col]     = acc[i][j][2];
            st[(row + 8) * 129 + col + 1] = acc[i][j][3];
        }
    }
    __syncthreads();

    int mt = n0 >> 10;                // 0=q, 1=k, 2=v
    int h0 = (n0 & 1023) >> 6;        // first head in this tile (even)
    int nbase = m0 & 2047;
    int bb = m0 >> 11;

    if (mt < 2) {
        int i  = tid & 31;
        int hh = (tid >> 5) & 1;
        int rg = tid >> 6;
        bf16* Hh = (mt == 0) ? Qh : Kh;
        bf16* Hl = (mt == 0) ? Ql : Kl;
        const float sc = (mt == 0) ? 0.125f * 1.44269504089f : 1.0f;
        size_t bhb = ((size_t)(bb * HH + h0 + hh)) * NN;
        int hcol = hh * 64;
#pragma unroll 4
        for (int rr = 0; rr < 32; rr++) {
            int r = rg * 32 + rr;
            int n = nbase + r;
            float v1 = st[r * 129 + hcol + i];
            float v2 = st[r * 129 + hcol + i + 32];
            float2 csv = *(const float2*)&cs[(n * 32 + i) * 2];
            float a1 = sc * (v1 * csv.x - v2 * csv.y);
            float a2 = sc * (v2 * csv.x + v1 * csv.y);
            size_t ob = (bhb + n) * 64;
            split2(a1, Hh, Hl, ob + i);
            split2(a2, Hh, Hl, ob + i + 32);
        }
    } else {
        int hh = tid >> 7;
        int dh = (tid >> 6) & 1;
        int np = (tid & 63) * 2;
        size_t vb = ((size_t)(bb * HH + h0 + hh)) * 64;
        int hcol = hh * 64;
#pragma unroll 4
        for (int dd = 0; dd < 32; dd++) {
            int d = dh * 32 + dd;
            float v0 = st[np * 129 + hcol + d];
            float v1 = st[(np + 1) * 129 + hcol + d];
            __nv_bfloat162 hv = __floats2bfloat162_rn(v0, v1);
            __nv_bfloat162 lv = __floats2bfloat162_rn(v0 - __bfloat162float(hv.x),
                                                      v1 - __bfloat162float(hv.y));
            size_t off = (vb + d) * NN + nbase + np;
            *(__nv_bfloat162*)&Vth[off] = hv;
            *(__nv_bfloat162*)&Vtl[off] = lv;
        }
    }
}

// ======================= fused flash attention (HMMA, bf16-split) ==============
// Per CTA: 64 q rows of one (b,h), 4 warps x 16 rows, 128 threads, 128B swizzle.
// Product-major MMA ordering in both S and PV phases.
__global__ __launch_bounds__(128, 3)
void flash_kernel(const bf16* __restrict__ Qh_, const bf16* __restrict__ Ql_,
                  const bf16* __restrict__ Kh_, const bf16* __restrict__ Kl_,
                  const bf16* __restrict__ Vh_, const bf16* __restrict__ Vl_,
                  bf16* __restrict__ aOh, bf16* __restrict__ aOl) {
    constexpr int FTILE = 8192;       // 64 rows x 128B, swizzled
    constexpr int FSTG  = 4 * FTILE;  // Kh,Kl,Vh,Vl

    extern __shared__ char smem[];
    uint32_t sb = smem_to_u32(smem);
    int tid = threadIdx.x, lane = tid & 31, wid = tid >> 5;
    int q0 = blockIdx.x * 64;
    int bh = blockIdx.y;
    int b = bh >> 4, h = bh & 15;

    const bf16* Qhp = Qh_ + ((size_t)bh * NN + q0) * 64;
    const bf16* Qlp = Ql_ + ((size_t)bh * NN + q0) * 64;
    const bf16* Khp = Kh_ + (size_t)bh * NN * 64;
    const bf16* Klp = Kl_ + (size_t)bh * NN * 64;
    const bf16* Vhp = Vh_ + (size_t)bh * 64 * NN;
    const bf16* Vlp = Vl_ + (size_t)bh * 64 * NN;

    // ---- prologue: stage Q (64x64 hi/lo) through stage-0 tiles 0/1 ----
#pragma unroll
    for (int it = 0; it < 4; it++) {
        int i = tid + it * 128;
        int r = i >> 3, c = i & 7;
        uint32_t so = sw128((uint32_t)(r * 128 + c * 16));
        cp16(sb + so, Qhp + r * 64 + c * 8);
        cp16(sb + FTILE + so, Qlp + r * 64 + c * 8);
    }
    asm volatile("cp.async.commit_group;" ::: "memory");

    auto load_kv = [&](int kt, int buf) {
        uint32_t base = sb + buf * FSTG;
        int kv0 = kt * 64;
#pragma unroll
        for (int it = 0; it < 16; it++) {
            int i = tid + it * 128;
            int mat = i >> 9;
            int slot = i & 511;
            int r = slot >> 3, c = slot & 7;
            uint32_t so = base + mat * FTILE + sw128((uint32_t)(r * 128 + c * 16));
            const bf16* g;
            if (mat == 0)      g = Khp + (size_t)(kv0 + r) * 64 + c * 8;
            else if (mat == 1) g = Klp + (size_t)(kv0 + r) * 64 + c * 8;
            else if (mat == 2) g = Vhp + (size_t)r * NN + kv0 + c * 8;
            else               g = Vlp + (size_t)r * NN + kv0 + c * 8;
            cp16(so, g);
        }
    };

    load_kv(0, 1);
    asm volatile("cp.async.commit_group;" ::: "memory");
    asm volatile("cp.async.wait_group 1;" ::: "memory");
    __syncthreads();

    uint32_t qh[4][4], ql[4][4];
    {
        int arow = wid * 16 + (lane & 15);
#pragma unroll
        for (int ks = 0; ks < 4; ks++) {
            int c16 = ks * 2 + (lane >> 4);
            uint32_t so = sw128((uint32_t)(arow * 128 + c16 * 16));
            ldm_x4(qh[ks], sb + so);
            ldm_x4(ql[ks], sb + FTILE + so);
        }
    }
    __syncthreads();

    float o[8][4];
#pragma unroll
    for (int j = 0; j < 8; j++)
#pragma unroll
        for (int c = 0; c < 4; c++) o[j][c] = 0.f;
    float lpart[2] = {0.f, 0.f};

    for (int kt = 0; kt < NN / 64; kt++) {
        int cur = (kt + 1) & 1;
        if (kt + 1 < NN / 64) {
            load_kv(kt + 1, kt & 1);
            asm volatile("cp.async.commit_group;" ::: "memory");
            asm volatile("cp.async.wait_group 1;" ::: "memory");
        } else {
            asm volatile("cp.async.wait_group 0;" ::: "memory");
        }
        __syncthreads();

        uint32_t kb = sb + cur * FSTG;
        uint32_t vb = kb + 2 * FTILE;

        // ---- S = Q @ K^T (0.125*log2e pre-folded into Q), product-major ----
        float s[8][4];
#pragma unroll
        for (int j = 0; j < 8; j++)
#pragma unroll
            for (int c = 0; c < 4; c++) s[j][c] = 0.f;
        {
            int brow = lane & 15;
#pragma unroll
            for (int ks = 0; ks < 4; ks++) {
                int c16 = ks * 2 + (lane >> 4);
                uint32_t khf[4][4], klf[4][4];
#pragma unroll
                for (int g = 0; g < 4; g++) {
                    uint32_t so = sw128((uint32_t)((g * 16 + brow) * 128 + c16 * 16));
                    ldm_x4(khf[g], kb + so);
                    ldm_x4(klf[g], kb + FTILE + so);
                }
#pragma unroll
                for (int g = 0; g < 4; g++)
#pragma unroll
                    for (int hf = 0; hf < 2; hf++)
                        mma16816(s[g * 2 + hf], qh[ks], khf[g][hf], khf[g][hf + 2]);
#pragma unroll
                for (int g = 0; g < 4; g++)
#pragma unroll
                    for (int hf = 0; hf < 2; hf++)
                        mma16816(s[g * 2 + hf], qh[ks], klf[g][hf], klf[g][hf + 2]);
#pragma unroll
                for (int g = 0; g < 4; g++)
#pragma unroll
                    for (int hf = 0; hf < 2; hf++)
                        mma16816(s[g * 2 + hf], ql[ks], khf[g][hf], khf[g][hf + 2]);
            }
        }

        // ---- per-kc: exp2 + partial sums + pack + PV (product-major) ----
        {
            int vrow = lane & 15;
#pragma unroll
            for (int kc = 0; kc < 4; kc++) {
                uint32_t pa[4], pl[4];
#pragma unroll
                for (int t = 0; t < 2; t++) {
                    int j = kc * 2 + t;
#pragma unroll
                    for (int e = 0; e < 4; e++) s[j][e] = ex2(s[j][e]);
                    lpart[0] += s[j][0] + s[j][1];
                    lpart[1] += s[j][2] + s[j][3];
#pragma unroll
                    for (int e = 0; e < 2; e++) {
                        float x = s[j][e * 2], y = s[j][e * 2 + 1];
                        __nv_bfloat162 hv = __floats2bfloat162_rn(x, y);
                        float lx = x - __bfloat162float(hv.x);
                        float ly = y - __bfloat162float(hv.y);
                        __nv_bfloat162 lv = __floats2bfloat162_rn(lx, ly);
                        pa[t * 2 + e] = *(uint32_t*)&hv;
                        pl[t * 2 + e] = *(uint32_t*)&lv;
                    }
                }
                uint32_t vhf[4][4], vlf[4][4];
#pragma unroll
                for (int g = 0; g < 4; g++) {
                    int c16 = kc * 2 + (lane >> 4);
                    uint32_t so = sw128((uint32_t)((g * 16 + vrow) * 128 + c16 * 16));
                    ldm_x4(vhf[g], vb + so);
                    ldm_x4(vlf[g], vb + FTILE + so);
                }
#pragma unroll
                for (int g = 0; g < 4; g++)
#pragma unroll
                    for (int hf = 0; hf < 2; hf++)
                        mma16816(o[g * 2 + hf], pa, vhf[g][hf], vhf[g][hf + 2]);
#pragma unroll
                for (int g = 0; g < 4; g++)
#pragma unroll
                    for (int hf = 0; hf < 2; hf++)
                        mma16816(o[g * 2 + hf], pl, vhf[g][hf], vhf[g][hf + 2]);
#pragma unroll
                for (int g = 0; g < 4; g++)
#pragma unroll
                    for (int hf = 0; hf < 2; hf++)
                        mma16816(o[g * 2 + hf], pa, vlf[g][hf], vlf[g][hf + 2]);
            }
        }
        __syncthreads();
    }

    // ---- epilogue: reduce row sums, normalize, split, write ----
    float lrow[2];
#pragma unroll
    for (int half = 0; half < 2; half++) {
        float rs = lpart[half];
        rs += __shfl_xor_sync(0xffffffffu, rs, 1);
        rs += __shfl_xor_sync(0xffffffffu, rs, 2);
        lrow[half] = rs;
    }
    float inv0 = 1.f / lrow[0], inv1 = 1.f / lrow[1];
    int r0 = q0 + wid * 16 + (lane >> 2);
    int cb = (lane & 3) * 2;
    size_t row0 = ((size_t)b * NN + r0) * 1024 + h * 64;
    size_t row1 = row0 + (size_t)8 * 1024;
#pragma unroll
    for (int dj = 0; dj < 8; dj++) {
        int col = dj * 8 + cb;
        float v0 = o[dj][0] * inv0, v1 = o[dj][1] * inv0;
        __nv_bfloat162 hv = __floats2bfloat162_rn(v0, v1);
        __nv_bfloat162 lv = __floats2bfloat162_rn(v0 - __bfloat162float(hv.x),
                                                  v1 - __bfloat162float(hv.y));
        *(__nv_bfloat162*)&aOh[row0 + col] = hv;
        *(__nv_bfloat162*)&aOl[row0 + col] = lv;
        float v2 = o[dj][2] * inv1, v3 = o[dj][3] * inv1;
        hv = __floats2bfloat162_rn(v2, v3);
        lv = __floats2bfloat162_rn(v2 - __bfloat162float(hv.x),
                                   v3 - __bfloat162float(hv.y));
        *(__nv_bfloat162*)&aOh[row1 + col] = hv;
        *(__nv_bfloat162*)&aOl[row1 + col] = lv;
    }
}

// ======================= small kernels =======================
__global__ void rope_table_kernel(float* __restrict__ cs) {
    int idx = blockIdx.x * blockDim.x + threadIdx.x;
    if (idx >= NN * 32) return;
    int n = idx >> 5, i = idx & 31;
    double inv = pow(10000.0, -(double)i / 32.0);
    double ang = (double)n * inv;
    cs[idx * 2]     = (float)cos(ang);
    cs[idx * 2 + 1] = (float)sin(ang);
}

__global__ void split_kernel(const float* __restrict__ src, bf16* __restrict__ H,
                             bf16* __restrict__ L, int n) {
    int i = (blockIdx.x * blockDim.x + threadIdx.x) * 4;
    if (i >= n) return;
    float4 v = *(const float4*)(src + i);
    __nv_bfloat162 h0 = __floats2bfloat162_rn(v.x, v.y);
    __nv_bfloat162 h1 = __floats2bfloat162_rn(v.z, v.w);
    __nv_bfloat162 l0 = __floats2bfloat162_rn(v.x - __bfloat162float(h0.x),
                                              v.y - __bfloat162float(h0.y));
    __nv_bfloat162 l1 = __floats2bfloat162_rn(v.z - __bfloat162float(h1.x),
                                              v.w - __bfloat162float(h1.y));
    *(__nv_bfloat162*)&H[i]     = h0;
    *(__nv_bfloat162*)&H[i + 2] = h1;
    *(__nv_bfloat162*)&L[i]     = l0;
    *(__nv_bfloat162*)&L[i + 2] = l1;
}

__global__ __launch_bounds__(256)
void wtrans_kernel(const float* __restrict__ W, bf16* __restrict__ Th,
                   bf16* __restrict__ Tl, int K, int N) {
    __shared__ float t[32][33];
    int n0 = blockIdx.x * 32, k0 = blockIdx.y * 32;
    int tx = threadIdx.x, ty = threadIdx.y;
#pragma unroll
    for (int s = 0; s < 32; s += 8)
        t[ty + s][tx] = W[(size_t)(k0 + ty + s) * N + n0 + tx];
    __syncthreads();
#pragma unroll
    for (int s = 0; s < 32; s += 8) {
        float v = t[tx][ty + s];
        split2(v, Th, Tl, (size_t)(n0 + ty + s) * K + k0 + tx);
    }
}

// ======================= launch =======================
extern "C" void kernel_launch(void* const* d_in, const int* in_sizes, int n_in,
                              void* d_out, int out_size) {
    const float* x     = (const float*)d_in[0];
    const float* w_qkv = (const float*)d_in[1];
    const float* w_out = (const float*)d_in[2];
    float* out = (float*)d_out;

    float *cs;
    bf16 *xh, *xl, *wqTh, *wqTl, *woTh, *woTl;
    bf16 *Qh, *Ql, *Kh, *Kl, *Vth, *Vtl, *aOh, *aOl;
    cudaGetSymbolAddress((void**)&cs,  g_cs);
    cudaGetSymbolAddress((void**)&xh,  g_xh);   cudaGetSymbolAddress((void**)&xl,  g_xl);
    cudaGetSymbolAddress((void**)&wqTh, g_wqTh); cudaGetSymbolAddress((void**)&wqTl, g_wqTl);
    cudaGetSymbolAddress((void**)&woTh, g_woTh); cudaGetSymbolAddress((void**)&woTl, g_woTl);
    cudaGetSymbolAddress((void**)&Qh, g_Qh);    cudaGetSymbolAddress((void**)&Ql, g_Ql);
    cudaGetSymbolAddress((void**)&Kh, g_Kh);    cudaGetSymbolAddress((void**)&Kl, g_Kl);
    cudaGetSymbolAddress((void**)&Vth, g_Vth);  cudaGetSymbolAddress((void**)&Vtl, g_Vtl);
    cudaGetSymbolAddress((void**)&aOh, g_aOh);  cudaGetSymbolAddress((void**)&aOl, g_aOl);

    const int SMEM_GEMM = 3 * (2 * 128 * 64 + 2 * 128 * 64);  // 98304 (>= 128*129*4)
    const int FLASH_SMEM = 2 * 4 * 8192;                       // 65536
    cudaFuncSetAttribute(mma_gemm_kernel<0>,
                         cudaFuncAttributeMaxDynamicSharedMemorySize, SMEM_GEMM);
    cudaFuncSetAttribute(mma_gemm_kernel<1>,
                         cudaFuncAttributeMaxDynamicSharedMemorySize, SMEM_GEMM);
    cudaFuncSetAttribute(flash_kernel,
                         cudaFuncAttributeMaxDynamicSharedMemorySize, FLASH_SMEM);

    // 0) rope table + split input / transpose weights
    rope_table_kernel<<<(NN * 32 + 255) / 256, 256>>>(cs);
    split_kernel<<<(MTOT * 1024 / 4 + 255) / 256, 256>>>(x, xh, xl, MTOT * 1024);
    wtrans_kernel<<<dim3(3072 / 32, 1024 / 32), dim3(32, 8)>>>(w_qkv, wqTh, wqTl, 1024, 3072);
    wtrans_kernel<<<dim3(1024 / 32, 1024 / 32), dim3(32, 8)>>>(w_out, woTh, woTl, 1024, 1024);

    // 1) qkv GEMM with fused rope/split/transpose epilogue
    mma_gemm_kernel<1><<<dim3(3072 / 128, 4096 / 128), 256, SMEM_GEMM>>>(
        xh, xl, wqTh, wqTl, nullptr, 1024, 0,
        cs, Qh, Ql, Kh, Kl, Vth, Vtl);

    // 2) fused flash attention -> aOh/aOl [B*N, 1024]
    flash_kernel<<<dim3(NN / 64, BHT), 128, FLASH_SMEM>>>(
        Qh, Ql, Kh, Kl, Vth, Vtl, aOh, aOl);

    // 3) out = aO @ w_out  (M=4096, N=1024, K=1024)
    mma_gemm_kernel<0><<<dim3(1024 / 128, 4096 / 128), 256, SMEM_GEMM>>>(
        aOh, aOl, woTh, woTl, out, 1024, 1024,
        nullptr, nullptr, nullptr, nullptr, nullptr, nullptr, nullptr);
}